// round 11
// baseline (speedup 1.0000x reference)
#include <cuda_runtime.h>
#include <cuda_bf16.h>
#include <cuda_fp16.h>

#define N_USERS 100000
#define N_ITEMS 150000
#define NN      250000
#define NFEAT   250002
#define NNZ     4000000
#define NNZ_H   2000000
#define EMB     64
#define BATCH   512
#define DMAX    256

#define SCAN_T  1024
#define SCAN_B  ((NN + SCAN_T - 1) / SCAN_T)   // 245

// padded row strides (in rows). Row NN of each X layer / row NFEAT of embH is a
// permanent zero row (device globals are zero-initialized, pad rows never written).
#define XROWS   (NN + 8)
#define EROWS   (NFEAT + 8)
#define ZROW_X  NN
#define ZROW_E  NFEAT

// ---------------- scratch (device globals; no runtime allocation) ------------
__device__ int    d_cnt[NN];
__device__ int    d_rowptr[NN + 1];
__device__ int    d_pos[NN];
__device__ int    d_col[NNZ];
__device__ int    d_bsum[SCAN_B];
__device__ int    d_boff[SCAN_B];
__device__ int    d_dhist[DMAX];
__device__ int    d_dhistI[DMAX];
__device__ int    d_perm[NN];
__device__ int    d_permI[N_ITEMS];
__device__ __half d_embH[(size_t)EROWS * EMB];
__device__ __half d_X[(size_t)3 * XROWS * EMB];   // pre-scaled reps x'_0..x'_2
__device__ __half d_Uh[BATCH * EMB];
__device__ __half d_Ih[(size_t)N_ITEMS * EMB];

// ---------------- emb -> fp16 ------------------------------------------------
__global__ void k_cvt_emb(const float* __restrict__ emb) {
    int i = blockIdx.x * blockDim.x + threadIdx.x;            // float4 index
    const int total = (NFEAT * EMB) / 4;
    if (i < total) {
        float4 f = ((const float4*)emb)[i];
        __half2 h0 = __floats2half2_rn(f.x, f.y);
        __half2 h1 = __floats2half2_rn(f.z, f.w);
        ((uint2*)d_embH)[i] = make_uint2(*(unsigned*)&h0, *(unsigned*)&h1);
    }
}

// ---------------- CSR build (mirror-compressed: read first 2M pairs) ---------
__global__ void k_hist(const int* __restrict__ row, const int* __restrict__ col) {
    int i = blockIdx.x * blockDim.x + threadIdx.x;
    int stride = gridDim.x * blockDim.x;
    for (; i < NNZ_H / 4; i += stride) {
        int4 r = ((const int4*)row)[i];
        int4 c = ((const int4*)col)[i];
        atomicAdd(&d_cnt[r.x], 1); atomicAdd(&d_cnt[c.x], 1);
        atomicAdd(&d_cnt[r.y], 1); atomicAdd(&d_cnt[c.y], 1);
        atomicAdd(&d_cnt[r.z], 1); atomicAdd(&d_cnt[c.z], 1);
        atomicAdd(&d_cnt[r.w], 1); atomicAdd(&d_cnt[c.w], 1);
    }
}

__device__ __forceinline__ int block_scan_incl(int v, int tid) {
    int lane = tid & 31, w = tid >> 5;
    int x = v;
    #pragma unroll
    for (int o = 1; o < 32; o <<= 1) {
        int y = __shfl_up_sync(0xffffffffu, x, o);
        if (lane >= o) x += y;
    }
    __shared__ int ws[32];
    if (lane == 31) ws[w] = x;
    __syncthreads();
    if (w == 0) {
        int y = ws[lane];
        #pragma unroll
        for (int o = 1; o < 32; o <<= 1) {
            int z = __shfl_up_sync(0xffffffffu, y, o);
            if (lane >= o) y += z;
        }
        ws[lane] = y;
    }
    __syncthreads();
    return x + (w > 0 ? ws[w - 1] : 0);
}

__global__ void k_csr1() {
    int tid = threadIdx.x;
    int i = blockIdx.x * SCAN_T + tid;
    int v = (i < NN) ? d_cnt[i] : 0;
    int incl = block_scan_incl(v, tid);
    if (tid == SCAN_T - 1) d_bsum[blockIdx.x] = incl;
}

__global__ void k_csr2() {
    int tid = threadIdx.x;
    int v = (tid < SCAN_B) ? d_bsum[tid] : 0;
    int lane = tid & 31, w = tid >> 5;
    int x = v;
    #pragma unroll
    for (int o = 1; o < 32; o <<= 1) {
        int y = __shfl_up_sync(0xffffffffu, x, o);
        if (lane >= o) x += y;
    }
    __shared__ int ws[8];
    if (lane == 31) ws[w] = x;
    __syncthreads();
    int off = 0;
    for (int j = 0; j < w; j++) off += ws[j];
    if (tid < SCAN_B) d_boff[tid] = x + off - v;
}

__global__ void k_csr3() {
    int tid = threadIdx.x;
    int i = blockIdx.x * SCAN_T + tid;
    int v = (i < NN) ? d_cnt[i] : 0;
    int incl = block_scan_incl(v, tid);
    int excl = incl - v + d_boff[blockIdx.x];
    if (i < NN) {
        d_rowptr[i] = excl;
        d_pos[i]    = excl;
        if (i == NN - 1) d_rowptr[NN] = excl + v;
    }
}

__global__ void k_scatter(const int* __restrict__ row, const int* __restrict__ col) {
    int i = blockIdx.x * blockDim.x + threadIdx.x;
    int stride = gridDim.x * blockDim.x;
    for (; i < NNZ_H / 4; i += stride) {
        int4 r = ((const int4*)row)[i];
        int4 c = ((const int4*)col)[i];
        int p;
        p = atomicAdd(&d_pos[r.x], 1); d_col[p] = c.x;
        p = atomicAdd(&d_pos[c.x], 1); d_col[p] = r.x;
        p = atomicAdd(&d_pos[r.y], 1); d_col[p] = c.y;
        p = atomicAdd(&d_pos[c.y], 1); d_col[p] = r.y;
        p = atomicAdd(&d_pos[r.z], 1); d_col[p] = c.z;
        p = atomicAdd(&d_pos[c.z], 1); d_col[p] = r.z;
        p = atomicAdd(&d_pos[r.w], 1); d_col[p] = c.w;
        p = atomicAdd(&d_pos[c.w], 1); d_col[p] = r.w;
    }
}

// ---------------- degree-bucketed permutation (counting sort by degree) ------
__global__ void k_dhist() {
    int i = blockIdx.x * blockDim.x + threadIdx.x;
    if (i < NN) {
        int deg = min(d_cnt[i], DMAX - 1);
        atomicAdd(&d_dhist[deg], 1);
        if (i >= N_USERS) atomicAdd(&d_dhistI[deg], 1);
    }
}

__global__ void k_dscan() {    // 1 block x 256: exclusive scan of both histograms
    int tid = threadIdx.x;
    int v = d_dhist[tid];
    int incl = block_scan_incl(v, tid);
    d_dhist[tid] = incl - v;
    __syncthreads();
    int vi = d_dhistI[tid];
    int incli = block_scan_incl(vi, tid);
    d_dhistI[tid] = incli - vi;
}

__global__ void k_dperm() {
    int i = blockIdx.x * blockDim.x + threadIdx.x;
    if (i < NN) {
        int deg = min(d_cnt[i], DMAX - 1);
        int p = atomicAdd(&d_dhist[deg], 1);
        d_perm[p] = i;
        if (i >= N_USERS) {
            int pI = atomicAdd(&d_dhistI[deg], 1);
            d_permI[pI] = i;
        }
    }
}

// ---- 8-lane helpers: lane l owns 8 consecutive halves (one uint4) of a row ---
__device__ __forceinline__ void row8_to_f(const __half* base, int node, int l,
                                          float* f /*8*/) {
    uint4 u = ((const uint4*)base)[node * 8 + l];
    float2 t;
    t = __half22float2(*(__half2*)&u.x); f[0] = t.x; f[1] = t.y;
    t = __half22float2(*(__half2*)&u.y); f[2] = t.x; f[3] = t.y;
    t = __half22float2(*(__half2*)&u.z); f[4] = t.x; f[5] = t.y;
    t = __half22float2(*(__half2*)&u.w); f[6] = t.x; f[7] = t.y;
}

__device__ __forceinline__ void store_row8(__half* base, size_t idx, const float* s) {
    __half2 h0 = __floats2half2_rn(s[0], s[1]);
    __half2 h1 = __floats2half2_rn(s[2], s[3]);
    __half2 h2 = __floats2half2_rn(s[4], s[5]);
    __half2 h3 = __floats2half2_rn(s[6], s[7]);
    ((uint4*)base)[idx] = make_uint4(*(unsigned*)&h0, *(unsigned*)&h1,
                                     *(unsigned*)&h2, *(unsigned*)&h3);
}

// ---- gather: 8 lanes per row, 4 rows per warp, fixed 8-deep inner loop -------
// out-of-row slots read the all-zeros pad row -> no masks anywhere.
__device__ __forceinline__ void nbr_sum8(const __half* in, int beg, int len,
                                         int maxlen, int gbase, int l, int zrow,
                                         float* s /*8, accumulated into*/) {
    const uint4* p = (const uint4*)in;
    for (int r0 = 0; r0 < maxlen; r0 += 8) {
        int jj = r0 + l;
        int c = (jj < len) ? d_col[beg + jj] : zrow;
        __half2 a0 = __float2half2_rn(0.f);
        __half2 a1 = __float2half2_rn(0.f);
        __half2 a2 = __float2half2_rn(0.f);
        __half2 a3 = __float2half2_rn(0.f);
        #pragma unroll
        for (int k = 0; k < 8; k++) {
            int cc = __shfl_sync(0xffffffffu, c, gbase + k);
            uint4 u = p[cc * 8 + l];
            a0 = __hadd2(a0, *(__half2*)&u.x);
            a1 = __hadd2(a1, *(__half2*)&u.y);
            a2 = __hadd2(a2, *(__half2*)&u.z);
            a3 = __hadd2(a3, *(__half2*)&u.w);
        }
        float2 t;
        t = __half22float2(a0); s[0] += t.x; s[1] += t.y;
        t = __half22float2(a1); s[2] += t.x; s[3] += t.y;
        t = __half22float2(a2); s[4] += t.x; s[5] += t.y;
        t = __half22float2(a3); s[6] += t.x; s[7] += t.y;
    }
}

// ---------------- layer 0: x'_0 = dinv * [rs^-0.5 * (sum embH[nbr]+embH[self]) * w]
__global__ void k_rep0(const float* __restrict__ w) {
    int lane = threadIdx.x & 31;
    int l = lane & 7;
    int gbase = lane & 24;
    int gi = (blockIdx.x * blockDim.x + threadIdx.x) >> 3;
    if (gi >= NN) return;
    int gw = d_perm[gi];
    int beg = d_rowptr[gw], end = d_rowptr[gw + 1];
    int len = end - beg;
    int maxlen = __reduce_max_sync(0xffffffffu, len);

    int self = NN + (gw >= N_USERS ? 1 : 0);
    float s[8];
    row8_to_f(d_embH, self, l, s);
    nbr_sum8(d_embH, beg, len, maxlen, gbase, l, ZROW_E, s);

    float fv = rsqrtf((float)(len + 1));
    float dinv = (len > 0) ? rsqrtf((float)len) : 1.f;
    float g = fv * dinv;
    float4 w0 = ((const float4*)w)[l * 2];
    float4 w1 = ((const float4*)w)[l * 2 + 1];
    s[0] *= g * w0.x; s[1] *= g * w0.y; s[2] *= g * w0.z; s[3] *= g * w0.w;
    s[4] *= g * w1.x; s[5] *= g * w1.y; s[6] *= g * w1.z; s[7] *= g * w1.w;
    store_row8(d_X, (size_t)gw * 8 + l, s);
}

// ---------------- adj SpMM layer (all nodes): x'_l = dinv^2 * sum x'_{l-1}[nbr]
__global__ void k_spmm(int layer) {
    const __half* in  = d_X + (size_t)(layer - 1) * XROWS * EMB;
    __half*       out = d_X + (size_t)layer * XROWS * EMB;
    int lane = threadIdx.x & 31;
    int l = lane & 7;
    int gbase = lane & 24;
    int gi = (blockIdx.x * blockDim.x + threadIdx.x) >> 3;
    if (gi >= NN) return;
    int gw = d_perm[gi];
    int beg = d_rowptr[gw], end = d_rowptr[gw + 1];
    int len = end - beg;
    int maxlen = __reduce_max_sync(0xffffffffu, len);

    float s[8] = {0.f, 0.f, 0.f, 0.f, 0.f, 0.f, 0.f, 0.f};
    nbr_sum8(in, beg, len, maxlen, gbase, l, ZROW_X, s);

    float di2 = (len > 0) ? (1.f / (float)len) : 1.f;
    #pragma unroll
    for (int j = 0; j < 8; j++) s[j] *= di2;
    store_row8(out, (size_t)gw * 8 + l, s);
}

// ---------------- layer 3 (items only) + combine -> d_Ih ----------------------
__global__ void k_spmm_item() {
    const __half* in = d_X + (size_t)2 * XROWS * EMB;
    int lane = threadIdx.x & 31;
    int l = lane & 7;
    int gbase = lane & 24;
    int gi = (blockIdx.x * blockDim.x + threadIdx.x) >> 3;
    if (gi >= N_ITEMS) return;
    int node = d_permI[gi];
    int it = node - N_USERS;
    int beg = d_rowptr[node], end = d_rowptr[node + 1];
    int len = end - beg;
    int maxlen = __reduce_max_sync(0xffffffffu, len);

    float s[8] = {0.f, 0.f, 0.f, 0.f, 0.f, 0.f, 0.f, 0.f};
    nbr_sum8(in, beg, len, maxlen, gbase, l, ZROW_X, s);
    float di2 = (len > 0) ? (1.f / (float)len) : 1.f;
    #pragma unroll
    for (int j = 0; j < 8; j++) s[j] *= di2;

    #pragma unroll
    for (int lay = 0; lay < 3; lay++) {
        float x[8];
        row8_to_f(d_X + (size_t)lay * XROWS * EMB, node, l, x);
        #pragma unroll
        for (int j = 0; j < 8; j++) s[j] += x[j];
    }
    float m = ((len > 0) ? sqrtf((float)len) : 1.f) * 0.25f;
    #pragma unroll
    for (int j = 0; j < 8; j++) s[j] *= m;
    store_row8(d_Ih, (size_t)it * 8 + l, s);
}

// ---------------- layer 3 (batch users only) + combine -> d_Uh ----------------
__global__ void k_finalU(const int* __restrict__ users) {
    const __half* in = d_X + (size_t)2 * XROWS * EMB;
    int lane = threadIdx.x & 31;
    int l = lane & 7;
    int gbase = lane & 24;
    int b = (blockIdx.x * blockDim.x + threadIdx.x) >> 3;
    if (b >= BATCH) return;
    int node = users[b];
    int beg = d_rowptr[node], end = d_rowptr[node + 1];
    int len = end - beg;
    int maxlen = __reduce_max_sync(0xffffffffu, len);

    float s[8] = {0.f, 0.f, 0.f, 0.f, 0.f, 0.f, 0.f, 0.f};
    nbr_sum8(in, beg, len, maxlen, gbase, l, ZROW_X, s);
    float di2 = (len > 0) ? (1.f / (float)len) : 1.f;
    #pragma unroll
    for (int j = 0; j < 8; j++) s[j] *= di2;

    #pragma unroll
    for (int lay = 0; lay < 3; lay++) {
        float x[8];
        row8_to_f(d_X + (size_t)lay * XROWS * EMB, node, l, x);
        #pragma unroll
        for (int j = 0; j < 8; j++) s[j] += x[j];
    }
    float m = ((len > 0) ? sqrtf((float)len) : 1.f) * 0.25f;
    #pragma unroll
    for (int j = 0; j < 8; j++) s[j] *= m;
    store_row8(d_Uh, (size_t)b * 8 + l, s);
}

// ---------------- tensor-core GEMM: out[512][150000] = Uh * Ih^T --------------
// block: 256 thr (8 warps), tile 128 users x 128 items, K=64; warp tile 32m x 64n
__device__ __forceinline__ unsigned smem_u32(const void* p) {
    return (unsigned)__cvta_generic_to_shared(p);
}

__global__ __launch_bounds__(256) void k_gemm_tc(float* __restrict__ out) {
    __shared__ __half Us[128][72];   // [m][k]
    __shared__ __half Is[128][72];   // [n][k]
    int tid = threadIdx.x;
    int wid = tid >> 5, lane = tid & 31;
    int it0 = blockIdx.x * 128;
    int u0  = blockIdx.y * 128;

    for (int i = tid; i < 128 * 8; i += 256) {
        int r = i >> 3, c = i & 7;
        *(uint4*)&Us[r][c * 8] = ((const uint4*)d_Uh)[(u0 + r) * 8 + c];
    }
    for (int i = tid; i < 128 * 8; i += 256) {
        int r = i >> 3, c = i & 7;
        int git = it0 + r;
        uint4 v = make_uint4(0u, 0u, 0u, 0u);
        if (git < N_ITEMS) v = ((const uint4*)d_Ih)[(size_t)git * 8 + c];
        *(uint4*)&Is[r][c * 8] = v;
    }
    __syncthreads();

    int wm = (wid & 3) * 32;
    int wn = (wid >> 2) * 64;

    float acc[2][8][4];
    #pragma unroll
    for (int mf = 0; mf < 2; mf++)
        #pragma unroll
        for (int n = 0; n < 8; n++)
            #pragma unroll
            for (int j = 0; j < 4; j++) acc[mf][n][j] = 0.f;

    #pragma unroll
    for (int ks = 0; ks < 4; ks++) {
        int k0 = ks * 16;
        unsigned a[2][4];
        #pragma unroll
        for (int mf = 0; mf < 2; mf++) {
            int rr = wm + mf * 16 + (lane & 15);
            int kk = k0 + (lane >> 4) * 8;
            unsigned addr = smem_u32(&Us[rr][kk]);
            asm volatile("ldmatrix.sync.aligned.m8n8.x4.shared.b16 {%0,%1,%2,%3}, [%4];"
                         : "=r"(a[mf][0]), "=r"(a[mf][1]), "=r"(a[mf][2]), "=r"(a[mf][3])
                         : "r"(addr));
        }
        #pragma unroll
        for (int nt = 0; nt < 8; nt += 2) {
            unsigned b0, b1, b2, b3;
            int sub = lane >> 3;
            int rr  = wn + nt * 8 + (lane & 7) + ((sub >> 1) * 8);
            int kk  = k0 + (sub & 1) * 8;
            unsigned addr = smem_u32(&Is[rr][kk]);
            asm volatile("ldmatrix.sync.aligned.m8n8.x4.shared.b16 {%0,%1,%2,%3}, [%4];"
                         : "=r"(b0), "=r"(b1), "=r"(b2), "=r"(b3) : "r"(addr));
            #pragma unroll
            for (int mf = 0; mf < 2; mf++) {
                asm volatile("mma.sync.aligned.m16n8k16.row.col.f32.f16.f16.f32 "
                             "{%0,%1,%2,%3}, {%4,%5,%6,%7}, {%8,%9}, {%0,%1,%2,%3};"
                             : "+f"(acc[mf][nt][0]), "+f"(acc[mf][nt][1]),
                               "+f"(acc[mf][nt][2]), "+f"(acc[mf][nt][3])
                             : "r"(a[mf][0]), "r"(a[mf][1]), "r"(a[mf][2]), "r"(a[mf][3]),
                               "r"(b0), "r"(b1));
                asm volatile("mma.sync.aligned.m16n8k16.row.col.f32.f16.f16.f32 "
                             "{%0,%1,%2,%3}, {%4,%5,%6,%7}, {%8,%9}, {%0,%1,%2,%3};"
                             : "+f"(acc[mf][nt+1][0]), "+f"(acc[mf][nt+1][1]),
                               "+f"(acc[mf][nt+1][2]), "+f"(acc[mf][nt+1][3])
                             : "r"(a[mf][0]), "r"(a[mf][1]), "r"(a[mf][2]), "r"(a[mf][3]),
                               "r"(b2), "r"(b3));
            }
        }
    }

    int cbase = it0 + wn + (lane & 3) * 2;
    #pragma unroll
    for (int mf = 0; mf < 2; mf++) {
        int m0 = u0 + wm + mf * 16 + (lane >> 2);
        #pragma unroll
        for (int nt = 0; nt < 8; nt++) {
            int col = cbase + nt * 8;
            if (col < N_ITEMS) {
                *(float2*)&out[(size_t)m0 * N_ITEMS + col] =
                    make_float2(acc[mf][nt][0], acc[mf][nt][1]);
                *(float2*)&out[(size_t)(m0 + 8) * N_ITEMS + col] =
                    make_float2(acc[mf][nt][2], acc[mf][nt][3]);
            }
        }
    }
}

// ---------------- launch -----------------------------------------------------
extern "C" void kernel_launch(void* const* d_in, const int* in_sizes, int n_in,
                              void* d_out, int out_size) {
    const int*   users = (const int*)  d_in[0];
    const float* emb   = (const float*)d_in[1];
    const float* w     = (const float*)d_in[2];
    const int*   arow  = (const int*)  d_in[3];
    const int*   acol  = (const int*)  d_in[4];
    float* out = (float*)d_out;

    void* p = nullptr;
    cudaGetSymbolAddress(&p, d_cnt);    cudaMemsetAsync(p, 0, NN * sizeof(int));
    cudaGetSymbolAddress(&p, d_dhist);  cudaMemsetAsync(p, 0, DMAX * sizeof(int));
    cudaGetSymbolAddress(&p, d_dhistI); cudaMemsetAsync(p, 0, DMAX * sizeof(int));

    k_cvt_emb<<<(NFEAT * EMB / 4 + 255) / 256, 256>>>(emb);
    k_hist<<<2048, 256>>>(arow, acol);
    k_csr1<<<SCAN_B, SCAN_T>>>();
    k_csr2<<<1, 256>>>();
    k_csr3<<<SCAN_B, SCAN_T>>>();
    k_scatter<<<2048, 256>>>(arow, acol);

    k_dhist<<<(NN + 255) / 256, 256>>>();
    k_dscan<<<1, 256>>>();
    k_dperm<<<(NN + 255) / 256, 256>>>();

    int blocks = (NN * 8 + 255) / 256;     // 8 lanes per row
    k_rep0<<<blocks, 256>>>(w);
    k_spmm<<<blocks, 256>>>(1);
    k_spmm<<<blocks, 256>>>(2);
    k_spmm_item<<<(N_ITEMS * 8 + 255) / 256, 256>>>();
    k_finalU<<<(BATCH * 8 + 255) / 256, 256>>>(users);

    dim3 g((N_ITEMS + 127) / 128, BATCH / 128);
    k_gemm_tc<<<g, 256>>>(out);
}

// round 12
// speedup vs baseline: 1.7072x; 1.7072x over previous
#include <cuda_runtime.h>
#include <cuda_bf16.h>
#include <cuda_fp16.h>

#define N_USERS 100000
#define N_ITEMS 150000
#define NN      250000
#define NFEAT   250002
#define NNZ     4000000
#define NNZ_H   2000000
#define EMB     64
#define BATCH   512

#define SCAN_T  1024
#define SCAN_B  ((NN + SCAN_T - 1) / SCAN_T)   // 245

// padded row strides (in rows). Row NN of each X layer / row NFEAT of embH is a
// permanent zero row (device globals are zero-initialized, pad rows never written).
#define XROWS   (NN + 8)
#define EROWS   (NFEAT + 8)
#define ZROW_X  NN
#define ZROW_E  NFEAT

// ---------------- scratch (device globals; no runtime allocation) ------------
__device__ int           d_cnt[NN];
__device__ int           d_rowptr[NN + 1];
__device__ int           d_col[NNZ];
__device__ unsigned char d_pb[NNZ];            // per-edge slot within its row
__device__ int           d_bsum[SCAN_B];
__device__ int           d_boff[SCAN_B];
__device__ __half        d_embH[(size_t)EROWS * EMB];
__device__ __half        d_X[(size_t)3 * XROWS * EMB];  // pre-scaled x'_0..x'_2
__device__ __half        d_Uh[BATCH * EMB];
__device__ __half        d_Ih[(size_t)N_ITEMS * EMB];

// ---------------- emb -> fp16 ------------------------------------------------
__global__ void k_cvt_emb(const float* __restrict__ emb) {
    int i = blockIdx.x * blockDim.x + threadIdx.x;            // float4 index
    const int total = (NFEAT * EMB) / 4;
    if (i < total) {
        float4 f = ((const float4*)emb)[i];
        __half2 h0 = __floats2half2_rn(f.x, f.y);
        __half2 h1 = __floats2half2_rn(f.z, f.w);
        ((uint2*)d_embH)[i] = make_uint2(*(unsigned*)&h0, *(unsigned*)&h1);
    }
}

// ---------------- CSR build pass 1: count + remember slot ---------------------
// mirror-compressed: reads the first 2M (row,col) pairs, emits both directions.
__global__ void k_hist(const int* __restrict__ row, const int* __restrict__ col) {
    int i = blockIdx.x * blockDim.x + threadIdx.x;
    int stride = gridDim.x * blockDim.x;
    for (; i < NNZ_H / 4; i += stride) {
        int4 r = ((const int4*)row)[i];
        int4 c = ((const int4*)col)[i];
        unsigned char pb[8];
        pb[0] = (unsigned char)atomicAdd(&d_cnt[r.x], 1);
        pb[1] = (unsigned char)atomicAdd(&d_cnt[c.x], 1);
        pb[2] = (unsigned char)atomicAdd(&d_cnt[r.y], 1);
        pb[3] = (unsigned char)atomicAdd(&d_cnt[c.y], 1);
        pb[4] = (unsigned char)atomicAdd(&d_cnt[r.z], 1);
        pb[5] = (unsigned char)atomicAdd(&d_cnt[c.z], 1);
        pb[6] = (unsigned char)atomicAdd(&d_cnt[r.w], 1);
        pb[7] = (unsigned char)atomicAdd(&d_cnt[c.w], 1);
        *(uint2*)&d_pb[(size_t)i * 8] = *(uint2*)pb;   // 8-byte coalesced store
    }
}

__device__ __forceinline__ int block_scan_incl(int v, int tid) {
    int lane = tid & 31, w = tid >> 5;
    int x = v;
    #pragma unroll
    for (int o = 1; o < 32; o <<= 1) {
        int y = __shfl_up_sync(0xffffffffu, x, o);
        if (lane >= o) x += y;
    }
    __shared__ int ws[32];
    if (lane == 31) ws[w] = x;
    __syncthreads();
    if (w == 0) {
        int y = ws[lane];
        #pragma unroll
        for (int o = 1; o < 32; o <<= 1) {
            int z = __shfl_up_sync(0xffffffffu, y, o);
            if (lane >= o) y += z;
        }
        ws[lane] = y;
    }
    __syncthreads();
    return x + (w > 0 ? ws[w - 1] : 0);
}

__global__ void k_csr1() {
    int tid = threadIdx.x;
    int i = blockIdx.x * SCAN_T + tid;
    int v = (i < NN) ? d_cnt[i] : 0;
    int incl = block_scan_incl(v, tid);
    if (tid == SCAN_T - 1) d_bsum[blockIdx.x] = incl;
}

__global__ void k_csr2() {
    int tid = threadIdx.x;
    int v = (tid < SCAN_B) ? d_bsum[tid] : 0;
    int lane = tid & 31, w = tid >> 5;
    int x = v;
    #pragma unroll
    for (int o = 1; o < 32; o <<= 1) {
        int y = __shfl_up_sync(0xffffffffu, x, o);
        if (lane >= o) x += y;
    }
    __shared__ int ws[8];
    if (lane == 31) ws[w] = x;
    __syncthreads();
    int off = 0;
    for (int j = 0; j < w; j++) off += ws[j];
    if (tid < SCAN_B) d_boff[tid] = x + off - v;
}

__global__ void k_csr3() {
    int tid = threadIdx.x;
    int i = blockIdx.x * SCAN_T + tid;
    int v = (i < NN) ? d_cnt[i] : 0;
    int incl = block_scan_incl(v, tid);
    int excl = incl - v + d_boff[blockIdx.x];
    if (i < NN) {
        d_rowptr[i] = excl;
        if (i == NN - 1) d_rowptr[NN] = excl + v;
    }
}

// ---------------- CSR build pass 2: atomic-free placement ---------------------
__global__ void k_place(const int* __restrict__ row, const int* __restrict__ col) {
    int i = blockIdx.x * blockDim.x + threadIdx.x;
    int stride = gridDim.x * blockDim.x;
    for (; i < NNZ_H / 4; i += stride) {
        int4 r = ((const int4*)row)[i];
        int4 c = ((const int4*)col)[i];
        uint2 pw = *(const uint2*)&d_pb[(size_t)i * 8];
        unsigned char pb[8];
        *(uint2*)pb = pw;
        d_col[d_rowptr[r.x] + pb[0]] = c.x;
        d_col[d_rowptr[c.x] + pb[1]] = r.x;
        d_col[d_rowptr[r.y] + pb[2]] = c.y;
        d_col[d_rowptr[c.y] + pb[3]] = r.y;
        d_col[d_rowptr[r.z] + pb[4]] = c.z;
        d_col[d_rowptr[c.z] + pb[5]] = r.z;
        d_col[d_rowptr[r.w] + pb[6]] = c.w;
        d_col[d_rowptr[c.w] + pb[7]] = r.w;
    }
}

// ---- 8-lane helpers: lane l owns 8 consecutive halves (one uint4) of a row ---
__device__ __forceinline__ void row8_to_f(const __half* base, int node, int l,
                                          float* f /*8*/) {
    uint4 u = ((const uint4*)base)[node * 8 + l];
    float2 t;
    t = __half22float2(*(__half2*)&u.x); f[0] = t.x; f[1] = t.y;
    t = __half22float2(*(__half2*)&u.y); f[2] = t.x; f[3] = t.y;
    t = __half22float2(*(__half2*)&u.z); f[4] = t.x; f[5] = t.y;
    t = __half22float2(*(__half2*)&u.w); f[6] = t.x; f[7] = t.y;
}

__device__ __forceinline__ void store_row8(__half* base, size_t idx, const float* s) {
    __half2 h0 = __floats2half2_rn(s[0], s[1]);
    __half2 h1 = __floats2half2_rn(s[2], s[3]);
    __half2 h2 = __floats2half2_rn(s[4], s[5]);
    __half2 h3 = __floats2half2_rn(s[6], s[7]);
    ((uint4*)base)[idx] = make_uint4(*(unsigned*)&h0, *(unsigned*)&h1,
                                     *(unsigned*)&h2, *(unsigned*)&h3);
}

// ---- gather: 8 lanes per row, 4 rows per warp, fixed 8-deep inner loop -------
// out-of-row slots read the all-zeros pad row -> no masks anywhere.
__device__ __forceinline__ void nbr_sum8(const __half* in, int beg, int len,
                                         int maxlen, int gbase, int l, int zrow,
                                         float* s /*8, accumulated into*/) {
    const uint4* p = (const uint4*)in;
    for (int r0 = 0; r0 < maxlen; r0 += 8) {
        int jj = r0 + l;
        int c = (jj < len) ? d_col[beg + jj] : zrow;
        __half2 a0 = __float2half2_rn(0.f);
        __half2 a1 = __float2half2_rn(0.f);
        __half2 a2 = __float2half2_rn(0.f);
        __half2 a3 = __float2half2_rn(0.f);
        #pragma unroll
        for (int k = 0; k < 8; k++) {
            int cc = __shfl_sync(0xffffffffu, c, gbase + k);
            uint4 u = p[cc * 8 + l];
            a0 = __hadd2(a0, *(__half2*)&u.x);
            a1 = __hadd2(a1, *(__half2*)&u.y);
            a2 = __hadd2(a2, *(__half2*)&u.z);
            a3 = __hadd2(a3, *(__half2*)&u.w);
        }
        float2 t;
        t = __half22float2(a0); s[0] += t.x; s[1] += t.y;
        t = __half22float2(a1); s[2] += t.x; s[3] += t.y;
        t = __half22float2(a2); s[4] += t.x; s[5] += t.y;
        t = __half22float2(a3); s[6] += t.x; s[7] += t.y;
    }
}

// ---------------- layer 0: x'_0 = dinv * [rs^-0.5 * (sum embH[nbr]+embH[self]) * w]
__global__ void k_rep0(const float* __restrict__ w) {
    int lane = threadIdx.x & 31;
    int l = lane & 7;
    int gbase = lane & 24;
    int gw = (blockIdx.x * blockDim.x + threadIdx.x) >> 3;
    if (gw >= NN) return;
    int beg = d_rowptr[gw], end = d_rowptr[gw + 1];
    int len = end - beg;
    int maxlen = __reduce_max_sync(0xffffffffu, len);

    int self = NN + (gw >= N_USERS ? 1 : 0);
    float s[8];
    row8_to_f(d_embH, self, l, s);
    nbr_sum8(d_embH, beg, len, maxlen, gbase, l, ZROW_E, s);

    float fv = rsqrtf((float)(len + 1));
    float dinv = (len > 0) ? rsqrtf((float)len) : 1.f;
    float g = fv * dinv;
    float4 w0 = ((const float4*)w)[l * 2];
    float4 w1 = ((const float4*)w)[l * 2 + 1];
    s[0] *= g * w0.x; s[1] *= g * w0.y; s[2] *= g * w0.z; s[3] *= g * w0.w;
    s[4] *= g * w1.x; s[5] *= g * w1.y; s[6] *= g * w1.z; s[7] *= g * w1.w;
    store_row8(d_X, (size_t)gw * 8 + l, s);
}

// ---------------- adj SpMM layer (all nodes): x'_l = dinv^2 * sum x'_{l-1}[nbr]
__global__ void k_spmm(int layer) {
    const __half* in  = d_X + (size_t)(layer - 1) * XROWS * EMB;
    __half*       out = d_X + (size_t)layer * XROWS * EMB;
    int lane = threadIdx.x & 31;
    int l = lane & 7;
    int gbase = lane & 24;
    int gw = (blockIdx.x * blockDim.x + threadIdx.x) >> 3;
    if (gw >= NN) return;
    int beg = d_rowptr[gw], end = d_rowptr[gw + 1];
    int len = end - beg;
    int maxlen = __reduce_max_sync(0xffffffffu, len);

    float s[8] = {0.f, 0.f, 0.f, 0.f, 0.f, 0.f, 0.f, 0.f};
    nbr_sum8(in, beg, len, maxlen, gbase, l, ZROW_X, s);

    float di2 = (len > 0) ? (1.f / (float)len) : 1.f;
    #pragma unroll
    for (int j = 0; j < 8; j++) s[j] *= di2;
    store_row8(out, (size_t)gw * 8 + l, s);
}

// ---------------- layer 3 (items only) + combine -> d_Ih ----------------------
__global__ void k_spmm_item() {
    const __half* in = d_X + (size_t)2 * XROWS * EMB;
    int lane = threadIdx.x & 31;
    int l = lane & 7;
    int gbase = lane & 24;
    int it = (blockIdx.x * blockDim.x + threadIdx.x) >> 3;
    if (it >= N_ITEMS) return;
    int node = N_USERS + it;
    int beg = d_rowptr[node], end = d_rowptr[node + 1];
    int len = end - beg;
    int maxlen = __reduce_max_sync(0xffffffffu, len);

    float s[8] = {0.f, 0.f, 0.f, 0.f, 0.f, 0.f, 0.f, 0.f};
    nbr_sum8(in, beg, len, maxlen, gbase, l, ZROW_X, s);
    float di2 = (len > 0) ? (1.f / (float)len) : 1.f;
    #pragma unroll
    for (int j = 0; j < 8; j++) s[j] *= di2;

    #pragma unroll
    for (int lay = 0; lay < 3; lay++) {
        float x[8];
        row8_to_f(d_X + (size_t)lay * XROWS * EMB, node, l, x);
        #pragma unroll
        for (int j = 0; j < 8; j++) s[j] += x[j];
    }
    float m = ((len > 0) ? sqrtf((float)len) : 1.f) * 0.25f;
    #pragma unroll
    for (int j = 0; j < 8; j++) s[j] *= m;
    store_row8(d_Ih, (size_t)it * 8 + l, s);
}

// ---------------- layer 3 (batch users only) + combine -> d_Uh ----------------
__global__ void k_finalU(const int* __restrict__ users) {
    const __half* in = d_X + (size_t)2 * XROWS * EMB;
    int lane = threadIdx.x & 31;
    int l = lane & 7;
    int gbase = lane & 24;
    int b = (blockIdx.x * blockDim.x + threadIdx.x) >> 3;
    if (b >= BATCH) return;
    int node = users[b];
    int beg = d_rowptr[node], end = d_rowptr[node + 1];
    int len = end - beg;
    int maxlen = __reduce_max_sync(0xffffffffu, len);

    float s[8] = {0.f, 0.f, 0.f, 0.f, 0.f, 0.f, 0.f, 0.f};
    nbr_sum8(in, beg, len, maxlen, gbase, l, ZROW_X, s);
    float di2 = (len > 0) ? (1.f / (float)len) : 1.f;
    #pragma unroll
    for (int j = 0; j < 8; j++) s[j] *= di2;

    #pragma unroll
    for (int lay = 0; lay < 3; lay++) {
        float x[8];
        row8_to_f(d_X + (size_t)lay * XROWS * EMB, node, l, x);
        #pragma unroll
        for (int j = 0; j < 8; j++) s[j] += x[j];
    }
    float m = ((len > 0) ? sqrtf((float)len) : 1.f) * 0.25f;
    #pragma unroll
    for (int j = 0; j < 8; j++) s[j] *= m;
    store_row8(d_Uh, (size_t)b * 8 + l, s);
}

// ---------------- tensor-core GEMM: out[512][150000] = Uh * Ih^T --------------
// block: 256 thr (8 warps), tile 128 users x 128 items, K=64; warp tile 32m x 64n
__device__ __forceinline__ unsigned smem_u32(const void* p) {
    return (unsigned)__cvta_generic_to_shared(p);
}

__global__ __launch_bounds__(256) void k_gemm_tc(float* __restrict__ out) {
    __shared__ __half Us[128][72];   // [m][k]
    __shared__ __half Is[128][72];   // [n][k]
    int tid = threadIdx.x;
    int wid = tid >> 5, lane = tid & 31;
    int it0 = blockIdx.x * 128;
    int u0  = blockIdx.y * 128;

    for (int i = tid; i < 128 * 8; i += 256) {
        int r = i >> 3, c = i & 7;
        *(uint4*)&Us[r][c * 8] = ((const uint4*)d_Uh)[(u0 + r) * 8 + c];
    }
    for (int i = tid; i < 128 * 8; i += 256) {
        int r = i >> 3, c = i & 7;
        int git = it0 + r;
        uint4 v = make_uint4(0u, 0u, 0u, 0u);
        if (git < N_ITEMS) v = ((const uint4*)d_Ih)[(size_t)git * 8 + c];
        *(uint4*)&Is[r][c * 8] = v;
    }
    __syncthreads();

    int wm = (wid & 3) * 32;
    int wn = (wid >> 2) * 64;

    float acc[2][8][4];
    #pragma unroll
    for (int mf = 0; mf < 2; mf++)
        #pragma unroll
        for (int n = 0; n < 8; n++)
            #pragma unroll
            for (int j = 0; j < 4; j++) acc[mf][n][j] = 0.f;

    #pragma unroll
    for (int ks = 0; ks < 4; ks++) {
        int k0 = ks * 16;
        unsigned a[2][4];
        #pragma unroll
        for (int mf = 0; mf < 2; mf++) {
            int rr = wm + mf * 16 + (lane & 15);
            int kk = k0 + (lane >> 4) * 8;
            unsigned addr = smem_u32(&Us[rr][kk]);
            asm volatile("ldmatrix.sync.aligned.m8n8.x4.shared.b16 {%0,%1,%2,%3}, [%4];"
                         : "=r"(a[mf][0]), "=r"(a[mf][1]), "=r"(a[mf][2]), "=r"(a[mf][3])
                         : "r"(addr));
        }
        #pragma unroll
        for (int nt = 0; nt < 8; nt += 2) {
            unsigned b0, b1, b2, b3;
            int sub = lane >> 3;
            int rr  = wn + nt * 8 + (lane & 7) + ((sub >> 1) * 8);
            int kk  = k0 + (sub & 1) * 8;
            unsigned addr = smem_u32(&Is[rr][kk]);
            asm volatile("ldmatrix.sync.aligned.m8n8.x4.shared.b16 {%0,%1,%2,%3}, [%4];"
                         : "=r"(b0), "=r"(b1), "=r"(b2), "=r"(b3) : "r"(addr));
            #pragma unroll
            for (int mf = 0; mf < 2; mf++) {
                asm volatile("mma.sync.aligned.m16n8k16.row.col.f32.f16.f16.f32 "
                             "{%0,%1,%2,%3}, {%4,%5,%6,%7}, {%8,%9}, {%0,%1,%2,%3};"
                             : "+f"(acc[mf][nt][0]), "+f"(acc[mf][nt][1]),
                               "+f"(acc[mf][nt][2]), "+f"(acc[mf][nt][3])
                             : "r"(a[mf][0]), "r"(a[mf][1]), "r"(a[mf][2]), "r"(a[mf][3]),
                               "r"(b0), "r"(b1));
                asm volatile("mma.sync.aligned.m16n8k16.row.col.f32.f16.f16.f32 "
                             "{%0,%1,%2,%3}, {%4,%5,%6,%7}, {%8,%9}, {%0,%1,%2,%3};"
                             : "+f"(acc[mf][nt+1][0]), "+f"(acc[mf][nt+1][1]),
                               "+f"(acc[mf][nt+1][2]), "+f"(acc[mf][nt+1][3])
                             : "r"(a[mf][0]), "r"(a[mf][1]), "r"(a[mf][2]), "r"(a[mf][3]),
                               "r"(b2), "r"(b3));
            }
        }
    }

    int cbase = it0 + wn + (lane & 3) * 2;
    #pragma unroll
    for (int mf = 0; mf < 2; mf++) {
        int m0 = u0 + wm + mf * 16 + (lane >> 2);
        #pragma unroll
        for (int nt = 0; nt < 8; nt++) {
            int col = cbase + nt * 8;
            if (col < N_ITEMS) {
                *(float2*)&out[(size_t)m0 * N_ITEMS + col] =
                    make_float2(acc[mf][nt][0], acc[mf][nt][1]);
                *(float2*)&out[(size_t)(m0 + 8) * N_ITEMS + col] =
                    make_float2(acc[mf][nt][2], acc[mf][nt][3]);
            }
        }
    }
}

// ---------------- launch -----------------------------------------------------
extern "C" void kernel_launch(void* const* d_in, const int* in_sizes, int n_in,
                              void* d_out, int out_size) {
    const int*   users = (const int*)  d_in[0];
    const float* emb   = (const float*)d_in[1];
    const float* w     = (const float*)d_in[2];
    const int*   arow  = (const int*)  d_in[3];
    const int*   acol  = (const int*)  d_in[4];
    float* out = (float*)d_out;

    void* p = nullptr;
    cudaGetSymbolAddress(&p, d_cnt);
    cudaMemsetAsync(p, 0, NN * sizeof(int));

    k_cvt_emb<<<(NFEAT * EMB / 4 + 255) / 256, 256>>>(emb);
    k_hist<<<2048, 256>>>(arow, acol);
    k_csr1<<<SCAN_B, SCAN_T>>>();
    k_csr2<<<1, 256>>>();
    k_csr3<<<SCAN_B, SCAN_T>>>();
    k_place<<<2048, 256>>>(arow, acol);

    int blocks = (NN * 8 + 255) / 256;     // 8 lanes per row
    k_rep0<<<blocks, 256>>>(w);
    k_spmm<<<blocks, 256>>>(1);
    k_spmm<<<blocks, 256>>>(2);
    k_spmm_item<<<(N_ITEMS * 8 + 255) / 256, 256>>>();
    k_finalU<<<(BATCH * 8 + 255) / 256, 256>>>(users);

    dim3 g((N_ITEMS + 127) / 128, BATCH / 128);
    k_gemm_tc<<<g, 256>>>(out);
}